// round 15
// baseline (speedup 1.0000x reference)
#include <cuda_runtime.h>
#include <cuda_bf16.h>
#include <math.h>
#include <stdint.h>

#define NN 100000
#define EE 1600000
#define EN (EE + NN)
#define HH 128
#define DEPTH 9
#define NB_SCAN 98   // ceil(NN/1024)
#define NLAYERS 17   // 9 up + 8 down 128x128 weight layers
#define NSLOTS 18    // BN stat slots

// ---- mma GEMM smem layout (R10 geometry, proven optimum) ----
#define ROWB 272
#define OFF_SC 0
#define OFF_SH 512
#define OFF_AH 1024
#define OFF_AL (OFF_AH + 128 * ROWB)
#define OFF_WH (OFF_AL + 128 * ROWB)
#define OFF_WL (OFF_WH + 128 * ROWB)
#define MMA_SMEM (OFF_WL + 128 * ROWB)     // 140288 bytes

// ----------------------------- device scratch -------------------------------
__device__ float g_xs[DEPTH][NN * HH];
__device__ float g_a[NN * HH];
__device__ float g_b[NN * HH];
__device__ __nv_bfloat16 g_cbf[NN * HH];   // bf16 shadow of GEMM output (agg gather src)
__device__ float g_ax[NN * 4];
__device__ float g_t1[NN];
__device__ float g_dinv[NN];
__device__ int   g_deg[NN];
__device__ int   g_incl[NN];
__device__ int   g_rowptr[NN];
__device__ int   g_fill[NN];
__device__ int   g_src[EE];
__device__ int   g_dst[EE];
__device__ int   g_col[EN];
__device__ float g_w[EN];
__device__ int   g_blocksum[128];
__device__ int   g_blockoff[128];
__device__ float g_sumA[NSLOTS][HH];
__device__ float g_sumsqA[NSLOTS][HH];
__device__ int   g_is32;
__device__ __nv_bfloat16 g_wall_hi[NLAYERS * HH * HH];
__device__ __nv_bfloat16 g_wall_lo[NLAYERS * HH * HH];

// --------------------------- edge dtype detection ---------------------------
__global__ void detect_dtype_kernel(const unsigned long long* __restrict__ p, int limit) {
    __shared__ int sfound;
    if (threadIdx.x == 0) sfound = 0;
    __syncthreads();
    int found = 0;
    for (int i = threadIdx.x; i < limit; i += blockDim.x)
        if (p[i] > 0xFFFFFFFFull) found = 1;
    if (found) sfound = 1;
    __syncthreads();
    if (threadIdx.x == 0) g_is32 = sfound;
}

// fused: edge convert + degree histogram
__global__ void convert_deg_kernel(const void* __restrict__ raw) {
    int e = blockIdx.x * blockDim.x + threadIdx.x;
    if (e >= EE) return;
    int s, d;
    if (g_is32) {
        const int* p = (const int*)raw;
        s = p[e]; d = p[EE + e];
    } else {
        const long long* p = (const long long*)raw;
        s = (int)p[e]; d = (int)p[EE + e];
    }
    g_src[e] = s;
    g_dst[e] = d;
    atomicAdd(&g_deg[d], 1);
}

// init: self-loop deg, fill counters, BN stat slots (folded)
__global__ void init_n_kernel() {
    int i = blockIdx.x * blockDim.x + threadIdx.x;
    if (i < NSLOTS * HH) {
        g_sumA[i >> 7][i & 127] = 0.f;
        g_sumsqA[i >> 7][i & 127] = 0.f;
    }
    if (i >= NN) return;
    g_deg[i] = 1;
    g_fill[i] = 0;
}

// scan1 also computes dinv (folded)
__global__ void scan1_kernel() {
    __shared__ int sh[1024];
    int tid = threadIdx.x;
    int i = blockIdx.x * 1024 + tid;
    int v = (i < NN) ? g_deg[i] : 0;
    if (i < NN) g_dinv[i] = rsqrtf((float)v);
    sh[tid] = v;
    __syncthreads();
    for (int off = 1; off < 1024; off <<= 1) {
        int t = (tid >= off) ? sh[tid - off] : 0;
        __syncthreads();
        sh[tid] += t;
        __syncthreads();
    }
    if (i < NN) g_incl[i] = sh[tid];
    if (tid == 1023) g_blocksum[blockIdx.x] = sh[1023];
}

__global__ void scan2_kernel() {
    __shared__ int sh[128];
    int tid = threadIdx.x;
    int v = (tid < NB_SCAN) ? g_blocksum[tid] : 0;
    sh[tid] = v;
    __syncthreads();
    for (int off = 1; off < 128; off <<= 1) {
        int t = (tid >= off) ? sh[tid - off] : 0;
        __syncthreads();
        sh[tid] += t;
        __syncthreads();
    }
    g_blockoff[tid] = sh[tid] - v;
}

__global__ void scan3_kernel() {
    int i = blockIdx.x * blockDim.x + threadIdx.x;
    if (i >= NN) return;
    g_rowptr[i] = g_incl[i] - g_deg[i] + g_blockoff[i >> 10];
}

// merged: edges then self loops
__global__ void fill_all_kernel() {
    int e = blockIdx.x * blockDim.x + threadIdx.x;
    if (e < EE) {
        int d = g_dst[e];
        int s = g_src[e];
        int pos = g_rowptr[d] + atomicAdd(&g_fill[d], 1);
        g_col[pos] = s;
        g_w[pos] = g_dinv[s] * g_dinv[d];
    } else if (e < EE + NN) {
        int i = e - EE;
        int pos = g_rowptr[i] + atomicAdd(&g_fill[i], 1);
        g_col[pos] = i;
        float dv = g_dinv[i];
        g_w[pos] = dv * dv;
    }
}

// -------- all-layers W pre-split: fp32 [k][n] -> bf16 hi/lo [n][k] ----------
__global__ void convw_all_kernel(const float* __restrict__ Ws1,
                                 const float* __restrict__ Ws2) {
    int idx = blockIdx.x * blockDim.x + threadIdx.x;
    if (idx >= NLAYERS * HH * HH) return;
    int l = idx >> 14;
    int r = idx & 16383;
    int k = r >> 7, n = r & 127;
    const float* W = (l < DEPTH) ? (Ws1 + (size_t)l * HH * HH)
                                 : (Ws2 + (size_t)(l - DEPTH) * HH * HH);
    float w = W[k * HH + n];
    __nv_bfloat16 h = __float2bfloat16_rn(w);
    float lo = w - __bfloat162float(h);
    g_wall_hi[l * HH * HH + n * HH + k] = h;
    g_wall_lo[l * HH * HH + n * HH + k] = __float2bfloat16_rn(lo);
}

// --------------------------- first layer (3-wide) ---------------------------
__global__ void agg3_kernel(const float* __restrict__ x) {
    int gid = blockIdx.x * blockDim.x + threadIdx.x;
    int node = gid >> 5, lane = gid & 31;
    if (node >= NN) return;
    int s0 = g_rowptr[node], cnt = g_deg[node];
    float a0 = 0.f, a1 = 0.f, a2 = 0.f;
    for (int e = s0 + lane; e < s0 + cnt; e += 32) {
        int s = g_col[e];
        float wt = g_w[e];
        a0 += wt * __ldg(&x[s * 3 + 0]);
        a1 += wt * __ldg(&x[s * 3 + 1]);
        a2 += wt * __ldg(&x[s * 3 + 2]);
    }
    for (int off = 16; off; off >>= 1) {
        a0 += __shfl_xor_sync(0xFFFFFFFFu, a0, off);
        a1 += __shfl_xor_sync(0xFFFFFFFFu, a1, off);
        a2 += __shfl_xor_sync(0xFFFFFFFFu, a2, off);
    }
    if (lane == 0) {
        g_ax[node * 4 + 0] = a0;
        g_ax[node * 4 + 1] = a1;
        g_ax[node * 4 + 2] = a2;
    }
}

// gemm3 with fused BN stats -> slot 0
__global__ void gemm3_stats_kernel(const float* __restrict__ W0, float* __restrict__ out) {
    __shared__ float w[3 * HH];
    __shared__ float ssum[8 * 128], ssq[8 * 128];
    for (int i = threadIdx.x; i < 3 * HH; i += blockDim.x) w[i] = W0[i];
    __syncthreads();
    int gid = blockIdx.x * blockDim.x + threadIdx.x;
    int node = gid >> 5;
    int lane = gid & 31, cg = lane * 4;
    int wrp = threadIdx.x >> 5;
    float a0 = g_ax[node * 4 + 0], a1 = g_ax[node * 4 + 1], a2 = g_ax[node * 4 + 2];
    float4 r;
    r.x = a0 * w[0 * HH + cg + 0] + a1 * w[1 * HH + cg + 0] + a2 * w[2 * HH + cg + 0];
    r.y = a0 * w[0 * HH + cg + 1] + a1 * w[1 * HH + cg + 1] + a2 * w[2 * HH + cg + 1];
    r.z = a0 * w[0 * HH + cg + 2] + a1 * w[1 * HH + cg + 2] + a2 * w[2 * HH + cg + 2];
    r.w = a0 * w[0 * HH + cg + 3] + a1 * w[1 * HH + cg + 3] + a2 * w[2 * HH + cg + 3];
    *(float4*)&out[node * HH + cg] = r;
    int base = wrp * 128 + cg;
    ssum[base + 0] = r.x; ssum[base + 1] = r.y; ssum[base + 2] = r.z; ssum[base + 3] = r.w;
    ssq[base + 0] = r.x * r.x; ssq[base + 1] = r.y * r.y;
    ssq[base + 2] = r.z * r.z; ssq[base + 3] = r.w * r.w;
    __syncthreads();
    if (threadIdx.x < 128) {
        float s = 0.f, s2 = 0.f;
        #pragma unroll
        for (int ww = 0; ww < 8; ++ww) {
            s  += ssum[ww * 128 + threadIdx.x];
            s2 += ssq[ww * 128 + threadIdx.x];
        }
        atomicAdd(&g_sumA[0][threadIdx.x], s);
        atomicAdd(&g_sumsqA[0][threadIdx.x], s2);
    }
}

// ------------- mma.sync bf16x3 GEMM, BN(from slot)+ReLU(+skip) fused ---------
// Also writes a bf16 shadow of C into g_cbf for the following aggregate.
__global__ void __launch_bounds__(256, 1) gemm_mma_kernel(
    const float* __restrict__ Araw, const float* __restrict__ skip,
    float* __restrict__ xstore, int lidx, int slot,
    const float* __restrict__ gamma, const float* __restrict__ beta,
    float* __restrict__ C, int n)
{
    extern __shared__ char smem[];
    float* sc = (float*)(smem + OFF_SC);
    float* sh = (float*)(smem + OFF_SH);

    int tid = threadIdx.x;
    int wid = tid >> 5, lane = tid & 31;
    int gid = lane >> 2, tig = lane & 3;
    int row0 = blockIdx.x * 128;

    if (tid < 128) {
        float m = g_sumA[slot][tid] * (1.f / NN);
        float var = g_sumsqA[slot][tid] * (1.f / NN) - m * m;
        float scv = gamma[tid] * rsqrtf(var + 1e-5f);
        sc[tid] = scv;
        sh[tid] = beta[tid] - m * scv;
    }
    {
        const uint4* gh = (const uint4*)(g_wall_hi + (size_t)lidx * HH * HH);
        const uint4* gl = (const uint4*)(g_wall_lo + (size_t)lidx * HH * HH);
        #pragma unroll
        for (int i = tid; i < 2048; i += 256) {
            int rw = i >> 4, sg = i & 15;
            *(uint4*)(smem + OFF_WH + rw * ROWB + sg * 16) = gh[i];
            *(uint4*)(smem + OFF_WL + rw * ROWB + sg * 16) = gl[i];
        }
    }
    __syncthreads();

    {
        int r  = tid >> 1;
        int kh = (tid & 1) << 6;
        int grow = row0 + r;
        bool valid = grow < n;
        const float* ap  = Araw + (size_t)grow * HH + kh;
        const float* spp = skip ? skip + (size_t)grow * HH + kh : (const float*)0;
        float* xp        = xstore ? xstore + (size_t)grow * HH + kh : (float*)0;
        const float* scp = sc + kh;
        const float* shp = sh + kh;
        #pragma unroll
        for (int j = 0; j < 8; ++j) {
            int k0 = j * 8;
            float4 va = make_float4(0.f, 0.f, 0.f, 0.f), vb = va;
            if (valid) {
                va = *(const float4*)(ap + k0);
                vb = *(const float4*)(ap + k0 + 4);
                float4 s0 = *(const float4*)(scp + k0);
                float4 s1 = *(const float4*)(scp + k0 + 4);
                float4 h0 = *(const float4*)(shp + k0);
                float4 h1 = *(const float4*)(shp + k0 + 4);
                va.x = fmaxf(va.x * s0.x + h0.x, 0.f);
                va.y = fmaxf(va.y * s0.y + h0.y, 0.f);
                va.z = fmaxf(va.z * s0.z + h0.z, 0.f);
                va.w = fmaxf(va.w * s0.w + h0.w, 0.f);
                vb.x = fmaxf(vb.x * s1.x + h1.x, 0.f);
                vb.y = fmaxf(vb.y * s1.y + h1.y, 0.f);
                vb.z = fmaxf(vb.z * s1.z + h1.z, 0.f);
                vb.w = fmaxf(vb.w * s1.w + h1.w, 0.f);
                if (xp) { *(float4*)(xp + k0) = va; *(float4*)(xp + k0 + 4) = vb; }
                if (spp) {
                    float4 u0 = *(const float4*)(spp + k0);
                    float4 u1 = *(const float4*)(spp + k0 + 4);
                    va.x += u0.x; va.y += u0.y; va.z += u0.z; va.w += u0.w;
                    vb.x += u1.x; vb.y += u1.y; vb.z += u1.z; vb.w += u1.w;
                }
            }
            float vals[8] = {va.x, va.y, va.z, va.w, vb.x, vb.y, vb.z, vb.w};
            uint32_t hp[4], lp[4];
            #pragma unroll
            for (int q = 0; q < 4; ++q) {
                __nv_bfloat16 e0 = __float2bfloat16_rn(vals[2 * q]);
                __nv_bfloat16 e1 = __float2bfloat16_rn(vals[2 * q + 1]);
                float l0 = vals[2 * q]     - __bfloat162float(e0);
                float l1 = vals[2 * q + 1] - __bfloat162float(e1);
                hp[q] = (uint32_t)__bfloat16_as_ushort(e0)
                      | ((uint32_t)__bfloat16_as_ushort(e1) << 16);
                lp[q] = (uint32_t)__bfloat16_as_ushort(__float2bfloat16_rn(l0))
                      | ((uint32_t)__bfloat16_as_ushort(__float2bfloat16_rn(l1)) << 16);
            }
            unsigned off = (unsigned)r * ROWB + (unsigned)(kh + k0) * 2;
            *(uint4*)(smem + OFF_AH + off) = make_uint4(hp[0], hp[1], hp[2], hp[3]);
            *(uint4*)(smem + OFF_AL + off) = make_uint4(lp[0], lp[1], lp[2], lp[3]);
        }
    }
    __syncthreads();

    int mr = wid & 3, nc = wid >> 2;
    float acc[2][8][4];
    #pragma unroll
    for (int mt = 0; mt < 2; ++mt)
        #pragma unroll
        for (int nt = 0; nt < 8; ++nt)
            #pragma unroll
            for (int q = 0; q < 4; ++q) acc[mt][nt][q] = 0.f;

    #pragma unroll
    for (int p = 0; p < 3; ++p) {
        const char* Ab = smem + ((p < 2) ? OFF_AH : OFF_AL);
        const char* Bb = smem + ((p == 1) ? OFF_WL : OFF_WH);
        #pragma unroll
        for (int s = 0; s < 8; ++s) {
            int k0 = s * 16;
            uint32_t a[2][4];
            #pragma unroll
            for (int mt = 0; mt < 2; ++mt) {
                int r = mr * 32 + mt * 16 + gid;
                const char* b0 = Ab + (unsigned)r * ROWB + (unsigned)(k0 + 2 * tig) * 2;
                const char* b1 = Ab + (unsigned)(r + 8) * ROWB + (unsigned)(k0 + 2 * tig) * 2;
                a[mt][0] = *(const uint32_t*)b0;
                a[mt][1] = *(const uint32_t*)b1;
                a[mt][2] = *(const uint32_t*)(b0 + 16);
                a[mt][3] = *(const uint32_t*)(b1 + 16);
            }
            uint32_t b[8][2];
            #pragma unroll
            for (int nt = 0; nt < 8; ++nt) {
                int nrow = nc * 64 + nt * 8 + gid;
                const char* bb = Bb + (unsigned)nrow * ROWB + (unsigned)(k0 + 2 * tig) * 2;
                b[nt][0] = *(const uint32_t*)bb;
                b[nt][1] = *(const uint32_t*)(bb + 16);
            }
            #pragma unroll
            for (int mt = 0; mt < 2; ++mt)
                #pragma unroll
                for (int nt = 0; nt < 8; ++nt) {
                    asm volatile(
                        "mma.sync.aligned.m16n8k16.row.col.f32.bf16.bf16.f32 "
                        "{%0,%1,%2,%3}, {%4,%5,%6,%7}, {%8,%9}, {%0,%1,%2,%3};"
                        : "+f"(acc[mt][nt][0]), "+f"(acc[mt][nt][1]),
                          "+f"(acc[mt][nt][2]), "+f"(acc[mt][nt][3])
                        : "r"(a[mt][0]), "r"(a[mt][1]), "r"(a[mt][2]), "r"(a[mt][3]),
                          "r"(b[nt][0]), "r"(b[nt][1]));
                }
        }
    }

    // epilogue: fp32 C + bf16 shadow
    #pragma unroll
    for (int mt = 0; mt < 2; ++mt) {
        int r0g = row0 + mr * 32 + mt * 16 + gid;
        #pragma unroll
        for (int nt = 0; nt < 8; ++nt) {
            int colb = nc * 64 + nt * 8 + 2 * tig;
            if (r0g < n) {
                float2 v; v.x = acc[mt][nt][0]; v.y = acc[mt][nt][1];
                *(float2*)&C[(size_t)r0g * HH + colb] = v;
                __nv_bfloat162 bv = __floats2bfloat162_rn(v.x, v.y);
                *(__nv_bfloat162*)&g_cbf[(size_t)r0g * HH + colb] = bv;
            }
            if (r0g + 8 < n) {
                float2 v; v.x = acc[mt][nt][2]; v.y = acc[mt][nt][3];
                *(float2*)&C[(size_t)(r0g + 8) * HH + colb] = v;
                __nv_bfloat162 bv = __floats2bfloat162_rn(v.x, v.y);
                *(__nv_bfloat162*)&g_cbf[(size_t)(r0g + 8) * HH + colb] = bv;
            }
        }
    }
}

// ----- 128-wide aggregate: gathers bf16 shadow, fp32 accum, fused stats -----
__global__ void __launch_bounds__(512) agg128_stats_kernel(
    float* __restrict__ hout, int slot)
{
    __shared__ float ssum[16 * 128], ssq[16 * 128];
    int gid = blockIdx.x * blockDim.x + threadIdx.x;
    int node = gid >> 5, lane = gid & 31;
    int wrp = threadIdx.x >> 5;
    int s0 = g_rowptr[node], cnt = g_deg[node];
    int e = s0, eend = s0 + cnt;
    const __nv_bfloat16* cb = g_cbf;
    float4 acc = make_float4(0.f, 0.f, 0.f, 0.f);
    // 8-wide unroll
    for (; e + 8 <= eend; e += 8) {
        int   si[8];
        float wv[8];
        #pragma unroll
        for (int q = 0; q < 8; ++q) { si[q] = g_col[e + q]; wv[q] = g_w[e + q]; }
        uint2 u[8];
        #pragma unroll
        for (int q = 0; q < 8; ++q)
            u[q] = __ldg((const uint2*)&cb[(size_t)si[q] * HH + lane * 4]);
        #pragma unroll
        for (int q = 0; q < 8; ++q) {
            float2 p0 = __bfloat1622float2(*(__nv_bfloat162*)&u[q].x);
            float2 p1 = __bfloat1622float2(*(__nv_bfloat162*)&u[q].y);
            acc.x += wv[q] * p0.x;
            acc.y += wv[q] * p0.y;
            acc.z += wv[q] * p1.x;
            acc.w += wv[q] * p1.y;
        }
    }
    for (; e < eend; ++e) {
        int s = g_col[e];
        float wt = g_w[e];
        uint2 u = __ldg((const uint2*)&cb[(size_t)s * HH + lane * 4]);
        float2 p0 = __bfloat1622float2(*(__nv_bfloat162*)&u.x);
        float2 p1 = __bfloat1622float2(*(__nv_bfloat162*)&u.y);
        acc.x += wt * p0.x; acc.y += wt * p0.y;
        acc.z += wt * p1.x; acc.w += wt * p1.y;
    }
    *(float4*)&hout[(size_t)node * HH + lane * 4] = acc;
    int base = wrp * 128 + lane * 4;
    ssum[base + 0] = acc.x; ssum[base + 1] = acc.y;
    ssum[base + 2] = acc.z; ssum[base + 3] = acc.w;
    ssq[base + 0] = acc.x * acc.x; ssq[base + 1] = acc.y * acc.y;
    ssq[base + 2] = acc.z * acc.z; ssq[base + 3] = acc.w * acc.w;
    __syncthreads();
    if (threadIdx.x < 128) {
        float s = 0.f, s2 = 0.f;
        #pragma unroll
        for (int ww = 0; ww < 16; ++ww) {
            s  += ssum[ww * 128 + threadIdx.x];
            s2 += ssq[ww * 128 + threadIdx.x];
        }
        atomicAdd(&g_sumA[slot][threadIdx.x], s);
        atomicAdd(&g_sumsqA[slot][threadIdx.x], s2);
    }
}

// ------------- final projection (BN from slot 17 + skip) + 1-wide agg --------
__global__ void outdot_kernel(const float* __restrict__ raw, const float* __restrict__ skip,
                              const float* __restrict__ Wout,
                              const float* __restrict__ gamma, const float* __restrict__ beta) {
    int gid = blockIdx.x * blockDim.x + threadIdx.x;
    int node = gid >> 5, lane = gid & 31;
    if (node >= NN) return;
    int cg = lane * 4;
    float4 scv, shv;
    {
        float4 sm = *(const float4*)&g_sumA[NSLOTS - 1][cg];
        float4 sq = *(const float4*)&g_sumsqA[NSLOTS - 1][cg];
        float4 gm = __ldg((const float4*)&gamma[cg]);
        float4 bt = __ldg((const float4*)&beta[cg]);
        float m0 = sm.x / NN, m1 = sm.y / NN, m2 = sm.z / NN, m3 = sm.w / NN;
        scv.x = gm.x * rsqrtf(sq.x / NN - m0 * m0 + 1e-5f);
        scv.y = gm.y * rsqrtf(sq.y / NN - m1 * m1 + 1e-5f);
        scv.z = gm.z * rsqrtf(sq.z / NN - m2 * m2 + 1e-5f);
        scv.w = gm.w * rsqrtf(sq.w / NN - m3 * m3 + 1e-5f);
        shv.x = bt.x - m0 * scv.x; shv.y = bt.y - m1 * scv.y;
        shv.z = bt.z - m2 * scv.z; shv.w = bt.w - m3 * scv.w;
    }
    float4 a = *(const float4*)&raw[(size_t)node * HH + cg];
    float4 s = *(const float4*)&skip[(size_t)node * HH + cg];
    a.x = fmaxf(a.x * scv.x + shv.x, 0.f) + s.x;
    a.y = fmaxf(a.y * scv.y + shv.y, 0.f) + s.y;
    a.z = fmaxf(a.z * scv.z + shv.z, 0.f) + s.z;
    a.w = fmaxf(a.w * scv.w + shv.w, 0.f) + s.w;
    float4 w = __ldg((const float4*)&Wout[cg]);
    float d = a.x * w.x + a.y * w.y + a.z * w.z + a.w * w.w;
    for (int off = 16; off; off >>= 1) d += __shfl_xor_sync(0xFFFFFFFFu, d, off);
    if (lane == 0) g_t1[node] = d;
}

__global__ void agg1_sigmoid_kernel(float* __restrict__ out) {
    int i = blockIdx.x * blockDim.x + threadIdx.x;
    if (i >= NN) return;
    int s0 = g_rowptr[i], cnt = g_deg[i];
    float acc = 0.f;
    for (int e = s0; e < s0 + cnt; ++e)
        acc += g_w[e] * __ldg(&g_t1[g_col[e]]);
    out[i] = 1.f / (1.f + expf(-acc));
}

// ---------------------------------- launch -----------------------------------
static inline float* sym_addr_f(const void* sym) {
    void* p = nullptr;
    cudaGetSymbolAddress(&p, sym);
    return (float*)p;
}

extern "C" void kernel_launch(void* const* d_in, const int* in_sizes, int n_in,
                              void* d_out, int out_size) {
    const float* x    = (const float*)d_in[0];
    const void*  ei   = d_in[1];
    const float* W0   = (const float*)d_in[2];
    const float* Ws1  = (const float*)d_in[3];
    const float* g1   = (const float*)d_in[4];
    const float* b1   = (const float*)d_in[5];
    const float* Ws2  = (const float*)d_in[6];
    const float* g2   = (const float*)d_in[7];
    const float* b2   = (const float*)d_in[8];
    const float* Wout = (const float*)d_in[9];
    float* out = (float*)d_out;

    float* xs = sym_addr_f(g_xs);
    float* pa = sym_addr_f(g_a);
    float* pb = sym_addr_f(g_b);

    static int smem_set = 0;
    if (!smem_set) {
        cudaFuncSetAttribute(gemm_mma_kernel,
                             cudaFuncAttributeMaxDynamicSharedMemorySize, MMA_SMEM);
        smem_set = 1;
    }

    const int TB = 256;
    const int gridE   = (EE + TB - 1) / TB;
    const int gridEN  = (EE + NN + TB - 1) / TB;
    const int gridN   = (NN + TB - 1) / TB;
    const int gridNW  = NN * 32 / 256;          // 12500
    const int gridNW5 = NN * 32 / 512;          // 6250
    const int gridG   = (NN + 127) / 128;       // 782

    // --- graph build ---
    detect_dtype_kernel<<<1, 256>>>((const unsigned long long*)ei, 2048);
    init_n_kernel<<<gridN, TB>>>();
    convert_deg_kernel<<<gridE, TB>>>(ei);
    scan1_kernel<<<NB_SCAN, 1024>>>();
    scan2_kernel<<<1, 128>>>();
    scan3_kernel<<<gridN, TB>>>();
    fill_all_kernel<<<gridEN, TB>>>();
    convw_all_kernel<<<(NLAYERS * HH * HH + 255) / 256, 256>>>(Ws1, Ws2);

    // --- layer 0 ---
    agg3_kernel<<<gridNW, TB>>>(x);
    gemm3_stats_kernel<<<gridNW, TB>>>(W0, pb);

    // --- up phase: i = 1..9 ---
    for (int i = 1; i <= DEPTH; ++i) {
        gemm_mma_kernel<<<gridG, 256, MMA_SMEM>>>(
            pb, nullptr, xs + (size_t)(i - 1) * NN * HH, i - 1, i - 1,
            g1 + (size_t)(i - 1) * HH, b1 + (size_t)(i - 1) * HH, pa, NN);
        agg128_stats_kernel<<<gridNW5, 512>>>(pb, i);
    }

    // --- down phase: i = 0..7 ---
    for (int i = 0; i < DEPTH - 1; ++i) {
        const float* skip = xs + (size_t)(DEPTH - 1 - i) * NN * HH;
        const float* gm = (i == 0) ? g1 + (size_t)DEPTH * HH : g2 + (size_t)(i - 1) * HH;
        const float* bt = (i == 0) ? b1 + (size_t)DEPTH * HH : b2 + (size_t)(i - 1) * HH;
        gemm_mma_kernel<<<gridG, 256, MMA_SMEM>>>(
            pb, skip, nullptr, DEPTH + i, DEPTH + i, gm, bt, pa, NN);
        agg128_stats_kernel<<<gridNW5, 512>>>(pb, DEPTH + 1 + i);
    }

    // --- final ---
    outdot_kernel<<<gridNW, TB>>>(pb, xs + 0, Wout,
                                  g2 + (size_t)(DEPTH - 2) * HH,
                                  b2 + (size_t)(DEPTH - 2) * HH);
    agg1_sigmoid_kernel<<<gridN, TB>>>(out);
}

// round 16
// speedup vs baseline: 1.6024x; 1.6024x over previous
#include <cuda_runtime.h>
#include <cuda_bf16.h>
#include <math.h>
#include <stdint.h>

#define NN 100000
#define EE 1600000
#define EN (EE + NN)
#define HH 128
#define DEPTH 9
#define NB_SCAN 98   // ceil(NN/1024)
#define NLAYERS 17   // 9 up + 8 down 128x128 weight layers
#define NSLOTS 18    // BN stat slots

// ---- mma GEMM smem layout (R10 geometry, proven optimum) ----
#define ROWB 272
#define OFF_SC 0
#define OFF_SH 512
#define OFF_AH 1024
#define OFF_AL (OFF_AH + 128 * ROWB)
#define OFF_WH (OFF_AL + 128 * ROWB)
#define OFF_WL (OFF_WH + 128 * ROWB)
#define MMA_SMEM (OFF_WL + 128 * ROWB)     // 140288 bytes

// ----------------------------- device scratch -------------------------------
__device__ float g_xs[DEPTH][NN * HH];
__device__ float g_b[NN * HH];
__device__ unsigned g_cbf[NN * HH / 2];    // bf16x2-packed shadow of GEMM output
__device__ float g_ax[NN * 4];
__device__ float g_t1[NN];
__device__ float g_dinv[NN];
__device__ int   g_deg[NN];
__device__ int   g_incl[NN];
__device__ int   g_rowptr[NN];
__device__ int   g_fill[NN];
__device__ int   g_src[EE];
__device__ int   g_dst[EE];
__device__ int   g_col[EN];
__device__ float g_w[EN];
__device__ int   g_blocksum[128];
__device__ int   g_blockoff[128];
__device__ float g_sumA[NSLOTS][HH];
__device__ float g_sumsqA[NSLOTS][HH];
__device__ int   g_is32;
__device__ __nv_bfloat16 g_wall_hi[NLAYERS * HH * HH];
__device__ __nv_bfloat16 g_wall_lo[NLAYERS * HH * HH];

// --------------------------- edge dtype detection ---------------------------
__global__ void detect_dtype_kernel(const unsigned long long* __restrict__ p, int limit) {
    __shared__ int sfound;
    if (threadIdx.x == 0) sfound = 0;
    __syncthreads();
    int found = 0;
    for (int i = threadIdx.x; i < limit; i += blockDim.x)
        if (p[i] > 0xFFFFFFFFull) found = 1;
    if (found) sfound = 1;
    __syncthreads();
    if (threadIdx.x == 0) g_is32 = sfound;
}

// fused: edge convert + degree histogram
__global__ void convert_deg_kernel(const void* __restrict__ raw) {
    int e = blockIdx.x * blockDim.x + threadIdx.x;
    if (e >= EE) return;
    int s, d;
    if (g_is32) {
        const int* p = (const int*)raw;
        s = p[e]; d = p[EE + e];
    } else {
        const long long* p = (const long long*)raw;
        s = (int)p[e]; d = (int)p[EE + e];
    }
    g_src[e] = s;
    g_dst[e] = d;
    atomicAdd(&g_deg[d], 1);
}

// init: self-loop deg, fill counters, BN stat slots (folded)
__global__ void init_n_kernel() {
    int i = blockIdx.x * blockDim.x + threadIdx.x;
    if (i < NSLOTS * HH) {
        g_sumA[i >> 7][i & 127] = 0.f;
        g_sumsqA[i >> 7][i & 127] = 0.f;
    }
    if (i >= NN) return;
    g_deg[i] = 1;
    g_fill[i] = 0;
}

// scan1 also computes dinv (folded)
__global__ void scan1_kernel() {
    __shared__ int sh[1024];
    int tid = threadIdx.x;
    int i = blockIdx.x * 1024 + tid;
    int v = (i < NN) ? g_deg[i] : 0;
    if (i < NN) g_dinv[i] = rsqrtf((float)v);
    sh[tid] = v;
    __syncthreads();
    for (int off = 1; off < 1024; off <<= 1) {
        int t = (tid >= off) ? sh[tid - off] : 0;
        __syncthreads();
        sh[tid] += t;
        __syncthreads();
    }
    if (i < NN) g_incl[i] = sh[tid];
    if (tid == 1023) g_blocksum[blockIdx.x] = sh[1023];
}

__global__ void scan2_kernel() {
    __shared__ int sh[128];
    int tid = threadIdx.x;
    int v = (tid < NB_SCAN) ? g_blocksum[tid] : 0;
    sh[tid] = v;
    __syncthreads();
    for (int off = 1; off < 128; off <<= 1) {
        int t = (tid >= off) ? sh[tid - off] : 0;
        __syncthreads();
        sh[tid] += t;
        __syncthreads();
    }
    g_blockoff[tid] = sh[tid] - v;
}

__global__ void scan3_kernel() {
    int i = blockIdx.x * blockDim.x + threadIdx.x;
    if (i >= NN) return;
    g_rowptr[i] = g_incl[i] - g_deg[i] + g_blockoff[i >> 10];
}

// merged: edges then self loops
__global__ void fill_all_kernel() {
    int e = blockIdx.x * blockDim.x + threadIdx.x;
    if (e < EE) {
        int d = g_dst[e];
        int s = g_src[e];
        int pos = g_rowptr[d] + atomicAdd(&g_fill[d], 1);
        g_col[pos] = s;
        g_w[pos] = g_dinv[s] * g_dinv[d];
    } else if (e < EE + NN) {
        int i = e - EE;
        int pos = g_rowptr[i] + atomicAdd(&g_fill[i], 1);
        g_col[pos] = i;
        float dv = g_dinv[i];
        g_w[pos] = dv * dv;
    }
}

// -------- all-layers W pre-split: fp32 [k][n] -> bf16 hi/lo [n][k] ----------
__global__ void convw_all_kernel(const float* __restrict__ Ws1,
                                 const float* __restrict__ Ws2) {
    int idx = blockIdx.x * blockDim.x + threadIdx.x;
    if (idx >= NLAYERS * HH * HH) return;
    int l = idx >> 14;
    int r = idx & 16383;
    int k = r >> 7, n = r & 127;
    const float* W = (l < DEPTH) ? (Ws1 + (size_t)l * HH * HH)
                                 : (Ws2 + (size_t)(l - DEPTH) * HH * HH);
    float w = W[k * HH + n];
    __nv_bfloat16 h = __float2bfloat16_rn(w);
    float lo = w - __bfloat162float(h);
    g_wall_hi[l * HH * HH + n * HH + k] = h;
    g_wall_lo[l * HH * HH + n * HH + k] = __float2bfloat16_rn(lo);
}

// --------------------------- first layer (3-wide) ---------------------------
__global__ void agg3_kernel(const float* __restrict__ x) {
    int gid = blockIdx.x * blockDim.x + threadIdx.x;
    int node = gid >> 5, lane = gid & 31;
    if (node >= NN) return;
    int s0 = g_rowptr[node], cnt = g_deg[node];
    float a0 = 0.f, a1 = 0.f, a2 = 0.f;
    for (int e = s0 + lane; e < s0 + cnt; e += 32) {
        int s = g_col[e];
        float wt = g_w[e];
        a0 += wt * __ldg(&x[s * 3 + 0]);
        a1 += wt * __ldg(&x[s * 3 + 1]);
        a2 += wt * __ldg(&x[s * 3 + 2]);
    }
    for (int off = 16; off; off >>= 1) {
        a0 += __shfl_xor_sync(0xFFFFFFFFu, a0, off);
        a1 += __shfl_xor_sync(0xFFFFFFFFu, a1, off);
        a2 += __shfl_xor_sync(0xFFFFFFFFu, a2, off);
    }
    if (lane == 0) {
        g_ax[node * 4 + 0] = a0;
        g_ax[node * 4 + 1] = a1;
        g_ax[node * 4 + 2] = a2;
    }
}

// gemm3 with fused BN stats -> slot 0
__global__ void gemm3_stats_kernel(const float* __restrict__ W0, float* __restrict__ out) {
    __shared__ float w[3 * HH];
    __shared__ float ssum[8 * 128], ssq[8 * 128];
    for (int i = threadIdx.x; i < 3 * HH; i += blockDim.x) w[i] = W0[i];
    __syncthreads();
    int gid = blockIdx.x * blockDim.x + threadIdx.x;
    int node = gid >> 5;
    int lane = gid & 31, cg = lane * 4;
    int wrp = threadIdx.x >> 5;
    float a0 = g_ax[node * 4 + 0], a1 = g_ax[node * 4 + 1], a2 = g_ax[node * 4 + 2];
    float4 r;
    r.x = a0 * w[0 * HH + cg + 0] + a1 * w[1 * HH + cg + 0] + a2 * w[2 * HH + cg + 0];
    r.y = a0 * w[0 * HH + cg + 1] + a1 * w[1 * HH + cg + 1] + a2 * w[2 * HH + cg + 1];
    r.z = a0 * w[0 * HH + cg + 2] + a1 * w[1 * HH + cg + 2] + a2 * w[2 * HH + cg + 2];
    r.w = a0 * w[0 * HH + cg + 3] + a1 * w[1 * HH + cg + 3] + a2 * w[2 * HH + cg + 3];
    *(float4*)&out[node * HH + cg] = r;
    int base = wrp * 128 + cg;
    ssum[base + 0] = r.x; ssum[base + 1] = r.y; ssum[base + 2] = r.z; ssum[base + 3] = r.w;
    ssq[base + 0] = r.x * r.x; ssq[base + 1] = r.y * r.y;
    ssq[base + 2] = r.z * r.z; ssq[base + 3] = r.w * r.w;
    __syncthreads();
    if (threadIdx.x < 128) {
        float s = 0.f, s2 = 0.f;
        #pragma unroll
        for (int ww = 0; ww < 8; ++ww) {
            s  += ssum[ww * 128 + threadIdx.x];
            s2 += ssq[ww * 128 + threadIdx.x];
        }
        atomicAdd(&g_sumA[0][threadIdx.x], s);
        atomicAdd(&g_sumsqA[0][threadIdx.x], s2);
    }
}

// ------------- mma.sync bf16x3 GEMM, BN(from slot)+ReLU(+skip) fused ---------
// Output: packed-bf16x2 shadow ONLY (consumed by the following aggregate).
__global__ void __launch_bounds__(256, 1) gemm_mma_kernel(
    const float* __restrict__ Araw, const float* __restrict__ skip,
    float* __restrict__ xstore, int lidx, int slot,
    const float* __restrict__ gamma, const float* __restrict__ beta, int n)
{
    extern __shared__ char smem[];
    float* sc = (float*)(smem + OFF_SC);
    float* sh = (float*)(smem + OFF_SH);

    int tid = threadIdx.x;
    int wid = tid >> 5, lane = tid & 31;
    int gid = lane >> 2, tig = lane & 3;
    int row0 = blockIdx.x * 128;

    if (tid < 128) {
        float m = g_sumA[slot][tid] * (1.f / NN);
        float var = g_sumsqA[slot][tid] * (1.f / NN) - m * m;
        float scv = gamma[tid] * rsqrtf(var + 1e-5f);
        sc[tid] = scv;
        sh[tid] = beta[tid] - m * scv;
    }
    {
        const uint4* gh = (const uint4*)(g_wall_hi + (size_t)lidx * HH * HH);
        const uint4* gl = (const uint4*)(g_wall_lo + (size_t)lidx * HH * HH);
        #pragma unroll
        for (int i = tid; i < 2048; i += 256) {
            int rw = i >> 4, sg = i & 15;
            *(uint4*)(smem + OFF_WH + rw * ROWB + sg * 16) = gh[i];
            *(uint4*)(smem + OFF_WL + rw * ROWB + sg * 16) = gl[i];
        }
    }
    __syncthreads();

    {
        int r  = tid >> 1;
        int kh = (tid & 1) << 6;
        int grow = row0 + r;
        bool valid = grow < n;
        const float* ap  = Araw + (size_t)grow * HH + kh;
        const float* spp = skip ? skip + (size_t)grow * HH + kh : (const float*)0;
        float* xp        = xstore ? xstore + (size_t)grow * HH + kh : (float*)0;
        const float* scp = sc + kh;
        const float* shp = sh + kh;
        #pragma unroll
        for (int j = 0; j < 8; ++j) {
            int k0 = j * 8;
            float4 va = make_float4(0.f, 0.f, 0.f, 0.f), vb = va;
            if (valid) {
                va = *(const float4*)(ap + k0);
                vb = *(const float4*)(ap + k0 + 4);
                float4 s0 = *(const float4*)(scp + k0);
                float4 s1 = *(const float4*)(scp + k0 + 4);
                float4 h0 = *(const float4*)(shp + k0);
                float4 h1 = *(const float4*)(shp + k0 + 4);
                va.x = fmaxf(va.x * s0.x + h0.x, 0.f);
                va.y = fmaxf(va.y * s0.y + h0.y, 0.f);
                va.z = fmaxf(va.z * s0.z + h0.z, 0.f);
                va.w = fmaxf(va.w * s0.w + h0.w, 0.f);
                vb.x = fmaxf(vb.x * s1.x + h1.x, 0.f);
                vb.y = fmaxf(vb.y * s1.y + h1.y, 0.f);
                vb.z = fmaxf(vb.z * s1.z + h1.z, 0.f);
                vb.w = fmaxf(vb.w * s1.w + h1.w, 0.f);
                if (xp) { *(float4*)(xp + k0) = va; *(float4*)(xp + k0 + 4) = vb; }
                if (spp) {
                    float4 u0 = *(const float4*)(spp + k0);
                    float4 u1 = *(const float4*)(spp + k0 + 4);
                    va.x += u0.x; va.y += u0.y; va.z += u0.z; va.w += u0.w;
                    vb.x += u1.x; vb.y += u1.y; vb.z += u1.z; vb.w += u1.w;
                }
            }
            float vals[8] = {va.x, va.y, va.z, va.w, vb.x, vb.y, vb.z, vb.w};
            uint32_t hp[4], lp[4];
            #pragma unroll
            for (int q = 0; q < 4; ++q) {
                __nv_bfloat16 e0 = __float2bfloat16_rn(vals[2 * q]);
                __nv_bfloat16 e1 = __float2bfloat16_rn(vals[2 * q + 1]);
                float l0 = vals[2 * q]     - __bfloat162float(e0);
                float l1 = vals[2 * q + 1] - __bfloat162float(e1);
                hp[q] = (uint32_t)__bfloat16_as_ushort(e0)
                      | ((uint32_t)__bfloat16_as_ushort(e1) << 16);
                lp[q] = (uint32_t)__bfloat16_as_ushort(__float2bfloat16_rn(l0))
                      | ((uint32_t)__bfloat16_as_ushort(__float2bfloat16_rn(l1)) << 16);
            }
            unsigned off = (unsigned)r * ROWB + (unsigned)(kh + k0) * 2;
            *(uint4*)(smem + OFF_AH + off) = make_uint4(hp[0], hp[1], hp[2], hp[3]);
            *(uint4*)(smem + OFF_AL + off) = make_uint4(lp[0], lp[1], lp[2], lp[3]);
        }
    }
    __syncthreads();

    int mr = wid & 3, nc = wid >> 2;
    float acc[2][8][4];
    #pragma unroll
    for (int mt = 0; mt < 2; ++mt)
        #pragma unroll
        for (int nt = 0; nt < 8; ++nt)
            #pragma unroll
            for (int q = 0; q < 4; ++q) acc[mt][nt][q] = 0.f;

    #pragma unroll
    for (int p = 0; p < 3; ++p) {
        const char* Ab = smem + ((p < 2) ? OFF_AH : OFF_AL);
        const char* Bb = smem + ((p == 1) ? OFF_WL : OFF_WH);
        #pragma unroll
        for (int s = 0; s < 8; ++s) {
            int k0 = s * 16;
            uint32_t a[2][4];
            #pragma unroll
            for (int mt = 0; mt < 2; ++mt) {
                int r = mr * 32 + mt * 16 + gid;
                const char* b0 = Ab + (unsigned)r * ROWB + (unsigned)(k0 + 2 * tig) * 2;
                const char* b1 = Ab + (unsigned)(r + 8) * ROWB + (unsigned)(k0 + 2 * tig) * 2;
                a[mt][0] = *(const uint32_t*)b0;
                a[mt][1] = *(const uint32_t*)b1;
                a[mt][2] = *(const uint32_t*)(b0 + 16);
                a[mt][3] = *(const uint32_t*)(b1 + 16);
            }
            uint32_t b[8][2];
            #pragma unroll
            for (int nt = 0; nt < 8; ++nt) {
                int nrow = nc * 64 + nt * 8 + gid;
                const char* bb = Bb + (unsigned)nrow * ROWB + (unsigned)(k0 + 2 * tig) * 2;
                b[nt][0] = *(const uint32_t*)bb;
                b[nt][1] = *(const uint32_t*)(bb + 16);
            }
            #pragma unroll
            for (int mt = 0; mt < 2; ++mt)
                #pragma unroll
                for (int nt = 0; nt < 8; ++nt) {
                    asm volatile(
                        "mma.sync.aligned.m16n8k16.row.col.f32.bf16.bf16.f32 "
                        "{%0,%1,%2,%3}, {%4,%5,%6,%7}, {%8,%9}, {%0,%1,%2,%3};"
                        : "+f"(acc[mt][nt][0]), "+f"(acc[mt][nt][1]),
                          "+f"(acc[mt][nt][2]), "+f"(acc[mt][nt][3])
                        : "r"(a[mt][0]), "r"(a[mt][1]), "r"(a[mt][2]), "r"(a[mt][3]),
                          "r"(b[nt][0]), "r"(b[nt][1]));
                }
        }
    }

    // ---- epilogue: packed bf16x2 shadow only (register-clean) ----
    #pragma unroll
    for (int mt = 0; mt < 2; ++mt) {
        int r0g = row0 + mr * 32 + mt * 16 + gid;
        #pragma unroll
        for (int nt = 0; nt < 8; ++nt) {
            int colb = nc * 64 + nt * 8 + 2 * tig;
            if (r0g < n) {
                uint32_t pk =
                    (uint32_t)__bfloat16_as_ushort(__float2bfloat16_rn(acc[mt][nt][0]))
                  | ((uint32_t)__bfloat16_as_ushort(__float2bfloat16_rn(acc[mt][nt][1])) << 16);
                g_cbf[((size_t)r0g * HH + colb) >> 1] = pk;
            }
            if (r0g + 8 < n) {
                uint32_t pk =
                    (uint32_t)__bfloat16_as_ushort(__float2bfloat16_rn(acc[mt][nt][2]))
                  | ((uint32_t)__bfloat16_as_ushort(__float2bfloat16_rn(acc[mt][nt][3])) << 16);
                g_cbf[((size_t)(r0g + 8) * HH + colb) >> 1] = pk;
            }
        }
    }
}

// ----- 128-wide aggregate: gathers packed bf16, fp32 accum, fused stats -----
// bf16 -> fp32 via 16-bit shift (exact, pure ALU, no address-taking).
__global__ void __launch_bounds__(512) agg128_stats_kernel(
    float* __restrict__ hout, int slot)
{
    __shared__ float ssum[16 * 128], ssq[16 * 128];
    int gid = blockIdx.x * blockDim.x + threadIdx.x;
    int node = gid >> 5, lane = gid & 31;
    int wrp = threadIdx.x >> 5;
    int s0 = g_rowptr[node], cnt = g_deg[node];
    int e = s0, eend = s0 + cnt;
    const unsigned* cb = g_cbf;
    float4 acc = make_float4(0.f, 0.f, 0.f, 0.f);
    // 8-wide unroll; each lane reads 2 packed words (4 bf16 = its 4 columns)
    for (; e + 8 <= eend; e += 8) {
        int   si[8];
        float wv[8];
        #pragma unroll
        for (int q = 0; q < 8; ++q) { si[q] = g_col[e + q]; wv[q] = g_w[e + q]; }
        uint2 u[8];
        #pragma unroll
        for (int q = 0; q < 8; ++q)
            u[q] = __ldg((const uint2*)(cb + (size_t)si[q] * (HH / 2) + lane * 2));
        #pragma unroll
        for (int q = 0; q < 8; ++q) {
            acc.x += wv[q] * __uint_as_float(u[q].x << 16);
            acc.y += wv[q] * __uint_as_float(u[q].x & 0xFFFF0000u);
            acc.z += wv[q] * __uint_as_float(u[q].y << 16);
            acc.w += wv[q] * __uint_as_float(u[q].y & 0xFFFF0000u);
        }
    }
    for (; e < eend; ++e) {
        int s = g_col[e];
        float wt = g_w[e];
        uint2 u = __ldg((const uint2*)(cb + (size_t)s * (HH / 2) + lane * 2));
        acc.x += wt * __uint_as_float(u.x << 16);
        acc.y += wt * __uint_as_float(u.x & 0xFFFF0000u);
        acc.z += wt * __uint_as_float(u.y << 16);
        acc.w += wt * __uint_as_float(u.y & 0xFFFF0000u);
    }
    *(float4*)&hout[(size_t)node * HH + lane * 4] = acc;
    int base = wrp * 128 + lane * 4;
    ssum[base + 0] = acc.x; ssum[base + 1] = acc.y;
    ssum[base + 2] = acc.z; ssum[base + 3] = acc.w;
    ssq[base + 0] = acc.x * acc.x; ssq[base + 1] = acc.y * acc.y;
    ssq[base + 2] = acc.z * acc.z; ssq[base + 3] = acc.w * acc.w;
    __syncthreads();
    if (threadIdx.x < 128) {
        float s = 0.f, s2 = 0.f;
        #pragma unroll
        for (int ww = 0; ww < 16; ++ww) {
            s  += ssum[ww * 128 + threadIdx.x];
            s2 += ssq[ww * 128 + threadIdx.x];
        }
        atomicAdd(&g_sumA[slot][threadIdx.x], s);
        atomicAdd(&g_sumsqA[slot][threadIdx.x], s2);
    }
}

// ------------- final projection (BN from slot 17 + skip) + 1-wide agg --------
__global__ void outdot_kernel(const float* __restrict__ raw, const float* __restrict__ skip,
                              const float* __restrict__ Wout,
                              const float* __restrict__ gamma, const float* __restrict__ beta) {
    int gid = blockIdx.x * blockDim.x + threadIdx.x;
    int node = gid >> 5, lane = gid & 31;
    if (node >= NN) return;
    int cg = lane * 4;
    float4 scv, shv;
    {
        float4 sm = *(const float4*)&g_sumA[NSLOTS - 1][cg];
        float4 sq = *(const float4*)&g_sumsqA[NSLOTS - 1][cg];
        float4 gm = __ldg((const float4*)&gamma[cg]);
        float4 bt = __ldg((const float4*)&beta[cg]);
        float m0 = sm.x / NN, m1 = sm.y / NN, m2 = sm.z / NN, m3 = sm.w / NN;
        scv.x = gm.x * rsqrtf(sq.x / NN - m0 * m0 + 1e-5f);
        scv.y = gm.y * rsqrtf(sq.y / NN - m1 * m1 + 1e-5f);
        scv.z = gm.z * rsqrtf(sq.z / NN - m2 * m2 + 1e-5f);
        scv.w = gm.w * rsqrtf(sq.w / NN - m3 * m3 + 1e-5f);
        shv.x = bt.x - m0 * scv.x; shv.y = bt.y - m1 * scv.y;
        shv.z = bt.z - m2 * scv.z; shv.w = bt.w - m3 * scv.w;
    }
    float4 a = *(const float4*)&raw[(size_t)node * HH + cg];
    float4 s = *(const float4*)&skip[(size_t)node * HH + cg];
    a.x = fmaxf(a.x * scv.x + shv.x, 0.f) + s.x;
    a.y = fmaxf(a.y * scv.y + shv.y, 0.f) + s.y;
    a.z = fmaxf(a.z * scv.z + shv.z, 0.f) + s.z;
    a.w = fmaxf(a.w * scv.w + shv.w, 0.f) + s.w;
    float4 w = __ldg((const float4*)&Wout[cg]);
    float d = a.x * w.x + a.y * w.y + a.z * w.z + a.w * w.w;
    for (int off = 16; off; off >>= 1) d += __shfl_xor_sync(0xFFFFFFFFu, d, off);
    if (lane == 0) g_t1[node] = d;
}

__global__ void agg1_sigmoid_kernel(float* __restrict__ out) {
    int i = blockIdx.x * blockDim.x + threadIdx.x;
    if (i >= NN) return;
    int s0 = g_rowptr[i], cnt = g_deg[i];
    float acc = 0.f;
    for (int e = s0; e < s0 + cnt; ++e)
        acc += g_w[e] * __ldg(&g_t1[g_col[e]]);
    out[i] = 1.f / (1.f + expf(-acc));
}

// ---------------------------------- launch -----------------------------------
static inline float* sym_addr_f(const void* sym) {
    void* p = nullptr;
    cudaGetSymbolAddress(&p, sym);
    return (float*)p;
}

extern "C" void kernel_launch(void* const* d_in, const int* in_sizes, int n_in,
                              void* d_out, int out_size) {
    const float* x    = (const float*)d_in[0];
    const void*  ei   = d_in[1];
    const float* W0   = (const float*)d_in[2];
    const float* Ws1  = (const float*)d_in[3];
    const float* g1   = (const float*)d_in[4];
    const float* b1   = (const float*)d_in[5];
    const float* Ws2  = (const float*)d_in[6];
    const float* g2   = (const float*)d_in[7];
    const float* b2   = (const float*)d_in[8];
    const float* Wout = (const float*)d_in[9];
    float* out = (float*)d_out;

    float* xs = sym_addr_f(g_xs);
    float* pb = sym_addr_f(g_b);

    static int smem_set = 0;
    if (!smem_set) {
        cudaFuncSetAttribute(gemm_mma_kernel,
                             cudaFuncAttributeMaxDynamicSharedMemorySize, MMA_SMEM);
        smem_set = 1;
    }

    const int TB = 256;
    const int gridE   = (EE + TB - 1) / TB;
    const int gridEN  = (EE + NN + TB - 1) / TB;
    const int gridN   = (NN + TB - 1) / TB;
    const int gridNW  = NN * 32 / 256;          // 12500
    const int gridNW5 = NN * 32 / 512;          // 6250
    const int gridG   = (NN + 127) / 128;       // 782

    // --- graph build ---
    detect_dtype_kernel<<<1, 256>>>((const unsigned long long*)ei, 2048);
    init_n_kernel<<<gridN, TB>>>();
    convert_deg_kernel<<<gridE, TB>>>(ei);
    scan1_kernel<<<NB_SCAN, 1024>>>();
    scan2_kernel<<<1, 128>>>();
    scan3_kernel<<<gridN, TB>>>();
    fill_all_kernel<<<gridEN, TB>>>();
    convw_all_kernel<<<(NLAYERS * HH * HH + 255) / 256, 256>>>(Ws1, Ws2);

    // --- layer 0 ---
    agg3_kernel<<<gridNW, TB>>>(x);
    gemm3_stats_kernel<<<gridNW, TB>>>(W0, pb);

    // --- up phase: i = 1..9 ---
    for (int i = 1; i <= DEPTH; ++i) {
        gemm_mma_kernel<<<gridG, 256, MMA_SMEM>>>(
            pb, nullptr, xs + (size_t)(i - 1) * NN * HH, i - 1, i - 1,
            g1 + (size_t)(i - 1) * HH, b1 + (size_t)(i - 1) * HH, NN);
        agg128_stats_kernel<<<gridNW5, 512>>>(pb, i);
    }

    // --- down phase: i = 0..7 ---
    for (int i = 0; i < DEPTH - 1; ++i) {
        const float* skip = xs + (size_t)(DEPTH - 1 - i) * NN * HH;
        const float* gm = (i == 0) ? g1 + (size_t)DEPTH * HH : g2 + (size_t)(i - 1) * HH;
        const float* bt = (i == 0) ? b1 + (size_t)DEPTH * HH : b2 + (size_t)(i - 1) * HH;
        gemm_mma_kernel<<<gridG, 256, MMA_SMEM>>>(
            pb, skip, nullptr, DEPTH + i, DEPTH + i, gm, bt, NN);
        agg128_stats_kernel<<<gridNW5, 512>>>(pb, DEPTH + 1 + i);
    }

    // --- final ---
    outdot_kernel<<<gridNW, TB>>>(pb, xs + 0, Wout,
                                  g2 + (size_t)(DEPTH - 2) * HH,
                                  b2 + (size_t)(DEPTH - 2) * HH);
    agg1_sigmoid_kernel<<<gridN, TB>>>(out);
}